// round 9
// baseline (speedup 1.0000x reference)
#include <cuda_runtime.h>
#include <math.h>
#include <stdint.h>

// Problem constants
#define BB 2
#define TT 1024
#define CC 1024
#define HH 16
#define LL 4
#define VV 50257
#define DD 64
#define FF 4096

// ---------------- scratch (device globals: allocation-guard safe) ----------
__device__ float g_x [BB*TT*CC];   // residual stream
__device__ float g_h [BB*TT*CC];   // LN output
__device__ float g_q [BB*TT*CC];
__device__ float g_k [BB*TT*CC];
__device__ float g_v [BB*TT*CC];
__device__ float g_y [BB*TT*CC];   // attention output
__device__ float g_h2[BB*TT*FF];   // MLP hidden

// ---------------- cp.async helpers ------------------------------------------
__device__ __forceinline__ uint32_t smem_u32(const void* p) {
    uint32_t a;
    asm("{ .reg .u64 t; cvta.to.shared.u64 t, %1; cvt.u32.u64 %0, t; }"
        : "=r"(a) : "l"(p));
    return a;
}
#define CP_ASYNC16(dst, src, sz) \
    asm volatile("cp.async.cg.shared.global [%0], [%1], 16, %2;" \
                 :: "r"(dst), "l"(src), "r"(sz) : "memory")
#define CP_COMMIT() asm volatile("cp.async.commit_group;" ::: "memory")
#define CP_WAIT1()  asm volatile("cp.async.wait_group 1;" ::: "memory")
#define CP_WAIT0()  asm volatile("cp.async.wait_group 0;" ::: "memory")

// mma.sync m16n8k8 tf32 (base PTX, HMMA path on sm_103)
__device__ __forceinline__ void mma_tf32(float& c0, float& c1, float& c2, float& c3,
                                         uint32_t a0, uint32_t a1, uint32_t a2, uint32_t a3,
                                         uint32_t b0, uint32_t b1) {
    asm volatile("mma.sync.aligned.m16n8k8.row.col.f32.tf32.tf32.f32 "
                 "{%0,%1,%2,%3}, {%4,%5,%6,%7}, {%8,%9}, {%0,%1,%2,%3};"
                 : "+f"(c0), "+f"(c1), "+f"(c2), "+f"(c3)
                 : "r"(a0), "r"(a1), "r"(a2), "r"(a3), "r"(b0), "r"(b1));
}

// exact tf32 split: hi = top-19-bit truncation (tf32-representable), lo = x - hi
__device__ __forceinline__ void split_tf32(float x, uint32_t& hi, uint32_t& lo) {
    uint32_t h = __float_as_uint(x) & 0xFFFFE000u;
    hi = h;
    lo = __float_as_uint(x - __uint_as_float(h));
}

// ---------------- tensor-core NT GEMM (3xTF32 compensated) -------------------
// C[m,n] = sum_k A[m,k]*B[n,k] (+bias +resid, GELU). A:[M,K], B:[N,K] row-major.
// 128x128 CTA tile, BK=32, 8 warps (4x2), warp tile 32x64.
// smem: padded stride 36 floats/row; 2-stage cp.async double buffer.
#define SROW 36
#define STAGE_F (2 * 128 * SROW)          // floats per stage (A tile + B tile)
#define GEMM_SMEM_BYTES (2 * STAGE_F * 4) // 73728 B

template<bool BIAS, bool RES, bool GELU_>
__global__ void __launch_bounds__(256)
gemm_mma(const float* __restrict__ A, const float* __restrict__ Bm,
         const float* __restrict__ bias, const float* __restrict__ resid,
         float* __restrict__ Cm, int M, int N, int K) {
    extern __shared__ float smem[];
    const int tid  = threadIdx.x;
    const int wid  = tid >> 5;
    const int lane = tid & 31;
    const int gr   = lane >> 2;     // 0..7
    const int qc   = lane & 3;      // 0..3
    const int warp_m = wid >> 1;    // 0..3
    const int warp_n = wid & 1;     // 0..1
    const int m0 = blockIdx.y * 128;
    const int n0 = blockIdx.x * 128;

    // loader mapping: row = tid>>1 (0..127), 4 float4 each
    const int lrow = tid >> 1;
    const int lq0  = (tid & 1) * 4;
    const float4* Arow = (const float4*)(A + (size_t)(m0 + lrow) * K);
    int brow = n0 + lrow;
    const uint32_t bsz = (brow < N) ? 16u : 0u;
    if (brow >= N) brow = n0;  // clamp to a valid address (size 0 => zero-fill)
    const float4* Brow = (const float4*)(Bm + (size_t)brow * K);

    const uint32_t sbase = smem_u32(smem);
    // stage s: A at s*STAGE_F, B at s*STAGE_F + 128*SROW (floats)
    uint32_t dA[2], dB[2];
    #pragma unroll
    for (int s = 0; s < 2; s++) {
        dA[s] = sbase + (s * STAGE_F) * 4            + lrow * (SROW*4) + lq0 * 16;
        dB[s] = sbase + (s * STAGE_F + 128*SROW) * 4 + lrow * (SROW*4) + lq0 * 16;
    }

    float c[2][8][4];
    #pragma unroll
    for (int mt = 0; mt < 2; mt++)
        #pragma unroll
        for (int nt = 0; nt < 8; nt++)
            #pragma unroll
            for (int r = 0; r < 4; r++) c[mt][nt][r] = 0.f;

    const int NK = K >> 5;

    // prefetch chunk 0 -> stage 0
    #pragma unroll
    for (int f = 0; f < 4; f++) {
        CP_ASYNC16(dA[0] + f * 16, Arow + lq0 + f, 16u);
        CP_ASYNC16(dB[0] + f * 16, Brow + lq0 + f, bsz);
    }
    CP_COMMIT();

    for (int i = 0; i < NK; i++) {
        const int s = i & 1;
        if (i + 1 < NK) {
            const int kq = (i + 1) << 3;   // float4 offset of next chunk
            #pragma unroll
            for (int f = 0; f < 4; f++) {
                CP_ASYNC16(dA[s ^ 1] + f * 16, Arow + kq + lq0 + f, 16u);
                CP_ASYNC16(dB[s ^ 1] + f * 16, Brow + kq + lq0 + f, bsz);
            }
            CP_COMMIT();
            CP_WAIT1();
        } else {
            CP_WAIT0();
        }
        __syncthreads();

        const float* As = smem + s * STAGE_F;
        const float* Bs = smem + s * STAGE_F + 128*SROW;

        #pragma unroll
        for (int ks = 0; ks < 4; ks++) {
            const int k0 = ks * 8;
            uint32_t afh[2][4], afl[2][4], bfh[8][2], bfl[8][2];
            #pragma unroll
            for (int mt = 0; mt < 2; mt++) {
                const int rb = warp_m * 32 + mt * 16 + gr;
                split_tf32(As[(rb    ) * SROW + k0 + qc    ], afh[mt][0], afl[mt][0]);
                split_tf32(As[(rb + 8) * SROW + k0 + qc    ], afh[mt][1], afl[mt][1]);
                split_tf32(As[(rb    ) * SROW + k0 + qc + 4], afh[mt][2], afl[mt][2]);
                split_tf32(As[(rb + 8) * SROW + k0 + qc + 4], afh[mt][3], afl[mt][3]);
            }
            #pragma unroll
            for (int nt = 0; nt < 8; nt++) {
                const int cb = warp_n * 64 + nt * 8 + gr;
                split_tf32(Bs[cb * SROW + k0 + qc    ], bfh[nt][0], bfl[nt][0]);
                split_tf32(Bs[cb * SROW + k0 + qc + 4], bfh[nt][1], bfl[nt][1]);
            }
            // pass 1: hi*hi
            #pragma unroll
            for (int mt = 0; mt < 2; mt++)
                #pragma unroll
                for (int nt = 0; nt < 8; nt++)
                    mma_tf32(c[mt][nt][0], c[mt][nt][1], c[mt][nt][2], c[mt][nt][3],
                             afh[mt][0], afh[mt][1], afh[mt][2], afh[mt][3],
                             bfh[nt][0], bfh[nt][1]);
            // pass 2: hi*lo
            #pragma unroll
            for (int mt = 0; mt < 2; mt++)
                #pragma unroll
                for (int nt = 0; nt < 8; nt++)
                    mma_tf32(c[mt][nt][0], c[mt][nt][1], c[mt][nt][2], c[mt][nt][3],
                             afh[mt][0], afh[mt][1], afh[mt][2], afh[mt][3],
                             bfl[nt][0], bfl[nt][1]);
            // pass 3: lo*hi
            #pragma unroll
            for (int mt = 0; mt < 2; mt++)
                #pragma unroll
                for (int nt = 0; nt < 8; nt++)
                    mma_tf32(c[mt][nt][0], c[mt][nt][1], c[mt][nt][2], c[mt][nt][3],
                             afl[mt][0], afl[mt][1], afl[mt][2], afl[mt][3],
                             bfh[nt][0], bfh[nt][1]);
        }
        __syncthreads();
    }

    // ---- epilogue ----
    #pragma unroll
    for (int mt = 0; mt < 2; mt++) {
        #pragma unroll
        for (int nt = 0; nt < 8; nt++) {
            #pragma unroll
            for (int half = 0; half < 2; half++) {
                const int m = m0 + warp_m * 32 + mt * 16 + gr + half * 8;
                #pragma unroll
                for (int e = 0; e < 2; e++) {
                    const int n = n0 + warp_n * 64 + nt * 8 + qc * 2 + e;
                    if (n < N) {
                        float v = c[mt][nt][half * 2 + e];
                        if (BIAS)  v += bias[n];
                        if (RES)   v += resid[(size_t)m * N + n];
                        if (GELU_) v = 0.5f * v * (1.0f + erff(v * 0.70710678118654752f));
                        Cm[(size_t)m * N + n] = v;
                    }
                }
            }
        }
    }
}

// ---------------- embedding -------------------------------------------------
__global__ void embed_kernel(const int* __restrict__ idx,
                             const float* __restrict__ tok,
                             const float* __restrict__ pos,
                             float* __restrict__ x) {
    int i = blockIdx.x * blockDim.x + threadIdx.x;
    if (i < BB*TT*CC) {
        int c  = i % CC;
        int bt = i / CC;
        int t  = bt % TT;
        x[i] = tok[(size_t)idx[bt] * CC + c] + pos[(size_t)t * CC + c];
    }
}

// ---------------- layernorm (one block per row of C=1024) ------------------
__global__ void ln_kernel(const float* __restrict__ in,
                          float* __restrict__ out,
                          const float* __restrict__ w,
                          const float* __restrict__ b) {
    int row = blockIdx.x;
    const float* xr = in + (size_t)row * CC;
    __shared__ float red[256];
    int tid = threadIdx.x;

    float s = 0.f;
    for (int i = tid; i < CC; i += 256) s += xr[i];
    red[tid] = s; __syncthreads();
    for (int o = 128; o > 0; o >>= 1) {
        if (tid < o) red[tid] += red[tid + o];
        __syncthreads();
    }
    float mu = red[0] * (1.0f / CC);
    __syncthreads();

    float vs = 0.f;
    for (int i = tid; i < CC; i += 256) { float d = xr[i] - mu; vs += d * d; }
    red[tid] = vs; __syncthreads();
    for (int o = 128; o > 0; o >>= 1) {
        if (tid < o) red[tid] += red[tid + o];
        __syncthreads();
    }
    float rstd = rsqrtf(red[0] * (1.0f / CC) + 1e-5f);

    for (int i = tid; i < CC; i += 256)
        out[(size_t)row * CC + i] = (xr[i] - mu) * rstd * w[i] + b[i];
}

// ---------------- attention: one block per (q-row, b*h) --------------------
__global__ void __launch_bounds__(128)
attn_kernel(const float* __restrict__ q, const float* __restrict__ k,
            const float* __restrict__ v, float* __restrict__ y) {
    int qpos = blockIdx.x;
    int bh = blockIdx.y;
    int b = bh / HH;
    int h = bh % HH;
    int tid = threadIdx.x;

    __shared__ float qs[DD];
    __shared__ float sc[TT];
    __shared__ float red[128];
    __shared__ float yacc[2][DD];

    const float* qp = q + ((size_t)(b * TT + qpos)) * CC + h * DD;
    if (tid < DD) qs[tid] = qp[tid];
    __syncthreads();

    int len = qpos + 1;
    const float scale = 0.125f;  // 1/sqrt(64)

    float mx = -1e30f;
    for (int j = tid; j < len; j += 128) {
        const float* kp = k + ((size_t)(b * TT + j)) * CC + h * DD;
        float dot = 0.f;
        #pragma unroll
        for (int d = 0; d < DD; d += 4) {
            float4 k4 = *(const float4*)(kp + d);
            dot = fmaf(qs[d + 0], k4.x, dot);
            dot = fmaf(qs[d + 1], k4.y, dot);
            dot = fmaf(qs[d + 2], k4.z, dot);
            dot = fmaf(qs[d + 3], k4.w, dot);
        }
        float s = dot * scale;
        sc[j] = s;
        mx = fmaxf(mx, s);
    }
    red[tid] = mx; __syncthreads();
    for (int o = 64; o > 0; o >>= 1) {
        if (tid < o) red[tid] = fmaxf(red[tid], red[tid + o]);
        __syncthreads();
    }
    mx = red[0];
    __syncthreads();

    float sum = 0.f;
    for (int j = tid; j < len; j += 128) {
        float e = __expf(sc[j] - mx);
        sc[j] = e;
        sum += e;
    }
    red[tid] = sum; __syncthreads();
    for (int o = 64; o > 0; o >>= 1) {
        if (tid < o) red[tid] += red[tid + o];
        __syncthreads();
    }
    float inv = 1.0f / red[0];
    __syncthreads();

    int g = tid >> 6;     // 0..1
    int d = tid & 63;
    float acc = 0.f;
    for (int j = g; j < len; j += 2)
        acc = fmaf(sc[j], v[((size_t)(b * TT + j)) * CC + h * DD + d], acc);
    yacc[g][d] = acc;
    __syncthreads();
    if (tid < DD)
        y[((size_t)(b * TT + qpos)) * CC + h * DD + tid] =
            (yacc[0][tid] + yacc[1][tid]) * inv;
}

// ---------------- host orchestration ---------------------------------------
static inline dim3 tc_grid(int M, int N) {
    return dim3((N + 127) / 128, (M + 127) / 128);
}

extern "C" void kernel_launch(void* const* d_in, const int* in_sizes, int n_in,
                              void* d_out, int out_size) {
    const int*   idx    = (const int*)  d_in[0];
    const float* tok    = (const float*)d_in[1];
    const float* pos    = (const float*)d_in[2];
    const float* ln1w   = (const float*)d_in[3];
    const float* ln1b   = (const float*)d_in[4];
    const float* Wq     = (const float*)d_in[5];
    const float* bq     = (const float*)d_in[6];
    const float* Wk     = (const float*)d_in[7];
    const float* bk     = (const float*)d_in[8];
    const float* Wv     = (const float*)d_in[9];
    const float* bv     = (const float*)d_in[10];
    const float* Wo     = (const float*)d_in[11];
    const float* bo     = (const float*)d_in[12];
    const float* ln2w   = (const float*)d_in[13];
    const float* ln2b   = (const float*)d_in[14];
    const float* W1     = (const float*)d_in[15];
    const float* b1     = (const float*)d_in[16];
    const float* W2     = (const float*)d_in[17];
    const float* b2     = (const float*)d_in[18];
    const float* lnfw   = (const float*)d_in[19];
    const float* lnfb   = (const float*)d_in[20];
    const float* head_w = (const float*)d_in[21];
    float* out = (float*)d_out;

    float *x, *h, *q, *k, *v, *y, *h2;
    cudaGetSymbolAddress((void**)&x,  g_x);
    cudaGetSymbolAddress((void**)&h,  g_h);
    cudaGetSymbolAddress((void**)&q,  g_q);
    cudaGetSymbolAddress((void**)&k,  g_k);
    cudaGetSymbolAddress((void**)&v,  g_v);
    cudaGetSymbolAddress((void**)&y,  g_y);
    cudaGetSymbolAddress((void**)&h2, g_h2);

    cudaFuncSetAttribute(gemm_mma<true,  false, false>, cudaFuncAttributeMaxDynamicSharedMemorySize, GEMM_SMEM_BYTES);
    cudaFuncSetAttribute(gemm_mma<true,  true,  false>, cudaFuncAttributeMaxDynamicSharedMemorySize, GEMM_SMEM_BYTES);
    cudaFuncSetAttribute(gemm_mma<true,  false, true >, cudaFuncAttributeMaxDynamicSharedMemorySize, GEMM_SMEM_BYTES);
    cudaFuncSetAttribute(gemm_mma<false, false, false>, cudaFuncAttributeMaxDynamicSharedMemorySize, GEMM_SMEM_BYTES);

    const int M = BB * TT;      // 2048

    embed_kernel<<<(BB*TT*CC + 255) / 256, 256>>>(idx, tok, pos, x);

    for (int l = 0; l < LL; l++) {
        const float* wq = Wq + (size_t)l * CC * CC;
        const float* wk = Wk + (size_t)l * CC * CC;
        const float* wv = Wv + (size_t)l * CC * CC;
        const float* wo = Wo + (size_t)l * CC * CC;
        const float* w1 = W1 + (size_t)l * FF * CC;
        const float* w2 = W2 + (size_t)l * CC * FF;

        ln_kernel<<<M, 256>>>(x, h, ln1w + (size_t)l * CC, ln1b + (size_t)l * CC);
        gemm_mma<true, false, false><<<tc_grid(M, CC), 256, GEMM_SMEM_BYTES>>>(h, wq, bq + (size_t)l * CC, nullptr, q, M, CC, CC);
        gemm_mma<true, false, false><<<tc_grid(M, CC), 256, GEMM_SMEM_BYTES>>>(h, wk, bk + (size_t)l * CC, nullptr, k, M, CC, CC);
        gemm_mma<true, false, false><<<tc_grid(M, CC), 256, GEMM_SMEM_BYTES>>>(h, wv, bv + (size_t)l * CC, nullptr, v, M, CC, CC);
        attn_kernel<<<dim3(TT, BB * HH), 128>>>(q, k, v, y);
        gemm_mma<true, true, false><<<tc_grid(M, CC), 256, GEMM_SMEM_BYTES>>>(y, wo, bo + (size_t)l * CC, x, x, M, CC, CC);
        ln_kernel<<<M, 256>>>(x, h, ln2w + (size_t)l * CC, ln2b + (size_t)l * CC);
        gemm_mma<true, false, true ><<<tc_grid(M, FF), 256, GEMM_SMEM_BYTES>>>(h, w1, b1 + (size_t)l * FF, nullptr, h2, M, FF, CC);
        gemm_mma<true, true, false><<<tc_grid(M, CC), 256, GEMM_SMEM_BYTES>>>(h2, w2, b2 + (size_t)l * CC, x, x, M, CC, FF);
    }

    ln_kernel<<<M, 256>>>(x, h, lnfw, lnfb);
    gemm_mma<false, false, false><<<tc_grid(M, VV), 256, GEMM_SMEM_BYTES>>>(h, head_w, nullptr, nullptr, out, M, VV, CC);
}

// round 11
// speedup vs baseline: 2.5904x; 2.5904x over previous
#include <cuda_runtime.h>
#include <cuda_bf16.h>
#include <math.h>
#include <stdint.h>

#define BB 2
#define TT 1024
#define CC 1024
#define HH 16
#define LL 4
#define VV 50257
#define DD 64
#define FF 4096

typedef __nv_bfloat16 bf16;

// ---------------- scratch (device globals) ----------------------------------
__device__ float g_x   [BB*TT*CC];       // residual stream (fp32)
__device__ float g_qkv [BB*TT*3*CC];     // fused qkv output (fp32)
__device__ float g_bqkv[LL*3*CC];        // concatenated qkv bias
__device__ bf16  g_hh [BB*TT*CC],  g_hl [BB*TT*CC];    // LN output planes
__device__ bf16  g_yh [BB*TT*CC],  g_yl [BB*TT*CC];    // attn output planes
__device__ bf16  g_h2h[BB*TT*FF],  g_h2l[BB*TT*FF];    // MLP hidden planes
__device__ bf16  g_wqkvh[LL*3*CC*CC], g_wqkvl[LL*3*CC*CC];
__device__ bf16  g_woh[LL*CC*CC],     g_wol[LL*CC*CC];
__device__ bf16  g_w1h[LL*FF*CC],     g_w1l[LL*FF*CC];
__device__ bf16  g_w2h[LL*CC*FF],     g_w2l[LL*CC*FF];
__device__ bf16  g_whh[(size_t)VV*CC], g_whl[(size_t)VV*CC];

// ---------------- helpers ----------------------------------------------------
__device__ __forceinline__ uint32_t smem_u32(const void* p) {
    uint32_t a;
    asm("{ .reg .u64 t; cvta.to.shared.u64 t, %1; cvt.u32.u64 %0, t; }"
        : "=r"(a) : "l"(p));
    return a;
}
#define CP_ASYNC16(dst, src, sz) \
    asm volatile("cp.async.cg.shared.global [%0], [%1], 16, %2;" \
                 :: "r"(dst), "l"(src), "r"(sz) : "memory")
#define CP_COMMIT() asm volatile("cp.async.commit_group;" ::: "memory")
#define CP_WAIT1()  asm volatile("cp.async.wait_group 1;" ::: "memory")
#define CP_WAIT0()  asm volatile("cp.async.wait_group 0;" ::: "memory")

__device__ __forceinline__ void split2(float x, bf16& h, bf16& l) {
    h = __float2bfloat16(x);                       // RN
    l = __float2bfloat16(x - __bfloat162float(h)); // RN residual
}

__device__ __forceinline__ void mma_bf16(float* c,
        uint32_t a0, uint32_t a1, uint32_t a2, uint32_t a3,
        uint32_t b0, uint32_t b1) {
    asm volatile("mma.sync.aligned.m16n8k16.row.col.f32.bf16.bf16.f32 "
                 "{%0,%1,%2,%3}, {%4,%5,%6,%7}, {%8,%9}, {%0,%1,%2,%3};"
                 : "+f"(c[0]), "+f"(c[1]), "+f"(c[2]), "+f"(c[3])
                 : "r"(a0), "r"(a1), "r"(a2), "r"(a3), "r"(b0), "r"(b1));
}

// ---------------- GEMM: C = A·B^T via bf16x2 3-term --------------------------
// A planes: [M,K] bf16 hi/lo; B planes: [N,K] bf16 hi/lo.
// 128x128 tile, BK=32, 8 warps (4x2), warp 32x64. 2-stage cp.async.
// smem row = 40 bf16 (80B) -> conflict-free frag loads (20r+qc distinct mod 32).
#define SROWB  80
#define PLANEB 10240      // 128*80
#define STAGEB 40960      // 4 planes (Ah, Al, Bh, Bl)
#define GEMM_SMEM (2*STAGEB)

template<bool BIAS, bool RES, bool GELU_, bool POUT>
__global__ void __launch_bounds__(256, 2)
gemm_mma(const bf16* __restrict__ Ah, const bf16* __restrict__ Al,
         const bf16* __restrict__ Bh, const bf16* __restrict__ Bl,
         const float* __restrict__ bias, const float* __restrict__ resid,
         float* __restrict__ Cf, bf16* __restrict__ Ch, bf16* __restrict__ Cl,
         int M, int N, int K) {
    extern __shared__ char sm[];
    const uint32_t sbase = smem_u32(sm);
    const int tid = threadIdx.x, lane = tid & 31, wid = tid >> 5;
    const int gr = lane >> 2, qc = lane & 3;
    const int warp_m = wid >> 1, warp_n = wid & 1;
    const int m0 = blockIdx.y * 128, n0 = blockIdx.x * 128;

    // loader: plane p = tid>>6 (Ah,Al,Bh,Bl), rows lr and lr+64, 4x16B chunks
    const int lp = tid >> 6, lr = tid & 63;
    const bf16* plane = (lp == 0) ? Ah : (lp == 1) ? Al : (lp == 2) ? Bh : Bl;
    const bool aP = lp < 2;
    int r0 = (aP ? m0 : n0) + lr;
    int r1 = r0 + 64;
    const uint32_t sz0 = (aP || r0 < N) ? 16u : 0u;
    const uint32_t sz1 = (aP || r1 < N) ? 16u : 0u;
    if (!aP) { if (r0 >= N) r0 = n0; if (r1 >= N) r1 = n0; }
    const char* src0 = (const char*)(plane + (size_t)r0 * K);
    const char* src1 = (const char*)(plane + (size_t)r1 * K);
    const uint32_t d0b = sbase + lp * PLANEB + lr * SROWB;
    const uint32_t d1b = d0b + 64 * SROWB;

    float c[2][8][4];
    #pragma unroll
    for (int mt = 0; mt < 2; mt++)
        #pragma unroll
        for (int nt = 0; nt < 8; nt++)
            #pragma unroll
            for (int r = 0; r < 4; r++) c[mt][nt][r] = 0.f;

    const int NK = K >> 5;

    #pragma unroll
    for (int cc2 = 0; cc2 < 4; cc2++) {
        CP_ASYNC16(d0b + cc2 * 16, src0 + cc2 * 16, sz0);
        CP_ASYNC16(d1b + cc2 * 16, src1 + cc2 * 16, sz1);
    }
    CP_COMMIT();

    for (int i = 0; i < NK; i++) {
        const int s = i & 1;
        if (i + 1 < NK) {
            const int kb = (i + 1) * 64;     // 32 bf16 = 64B per row-chunk
            const uint32_t ds = (uint32_t)(s ^ 1) * STAGEB;
            #pragma unroll
            for (int cc2 = 0; cc2 < 4; cc2++) {
                CP_ASYNC16(d0b + ds + cc2 * 16, src0 + kb + cc2 * 16, sz0);
                CP_ASYNC16(d1b + ds + cc2 * 16, src1 + kb + cc2 * 16, sz1);
            }
            CP_COMMIT();
            CP_WAIT1();
        } else {
            CP_WAIT0();
        }
        __syncthreads();

        const char* st = sm + s * STAGEB;
        #pragma unroll
        for (int ks = 0; ks < 2; ks++) {
            uint32_t ah[2][4], alr[2][4], bh[8][2], blr[8][2];
            #pragma unroll
            for (int mt = 0; mt < 2; mt++) {
                const int rb = warp_m * 32 + mt * 16 + gr;
                const char* p = st + rb * SROWB + ks * 32 + qc * 4;
                ah[mt][0] = *(const uint32_t*)(p);
                ah[mt][1] = *(const uint32_t*)(p + 8 * SROWB);
                ah[mt][2] = *(const uint32_t*)(p + 16);
                ah[mt][3] = *(const uint32_t*)(p + 8 * SROWB + 16);
                const char* q = p + PLANEB;
                alr[mt][0] = *(const uint32_t*)(q);
                alr[mt][1] = *(const uint32_t*)(q + 8 * SROWB);
                alr[mt][2] = *(const uint32_t*)(q + 16);
                alr[mt][3] = *(const uint32_t*)(q + 8 * SROWB + 16);
            }
            #pragma unroll
            for (int nt = 0; nt < 8; nt++) {
                const int cb = warp_n * 64 + nt * 8 + gr;
                const char* p = st + 2 * PLANEB + cb * SROWB + ks * 32 + qc * 4;
                bh[nt][0]  = *(const uint32_t*)(p);
                bh[nt][1]  = *(const uint32_t*)(p + 16);
                blr[nt][0] = *(const uint32_t*)(p + PLANEB);
                blr[nt][1] = *(const uint32_t*)(p + PLANEB + 16);
            }
            #pragma unroll
            for (int mt = 0; mt < 2; mt++)
                #pragma unroll
                for (int nt = 0; nt < 8; nt++)
                    mma_bf16(c[mt][nt], ah[mt][0], ah[mt][1], ah[mt][2], ah[mt][3],
                             bh[nt][0], bh[nt][1]);
            #pragma unroll
            for (int mt = 0; mt < 2; mt++)
                #pragma unroll
                for (int nt = 0; nt < 8; nt++)
                    mma_bf16(c[mt][nt], ah[mt][0], ah[mt][1], ah[mt][2], ah[mt][3],
                             blr[nt][0], blr[nt][1]);
            #pragma unroll
            for (int mt = 0; mt < 2; mt++)
                #pragma unroll
                for (int nt = 0; nt < 8; nt++)
                    mma_bf16(c[mt][nt], alr[mt][0], alr[mt][1], alr[mt][2], alr[mt][3],
                             bh[nt][0], bh[nt][1]);
        }
        __syncthreads();
    }

    // epilogue
    #pragma unroll
    for (int mt = 0; mt < 2; mt++) {
        #pragma unroll
        for (int nt = 0; nt < 8; nt++) {
            #pragma unroll
            for (int half = 0; half < 2; half++) {
                const int m = m0 + warp_m * 32 + mt * 16 + gr + half * 8;
                #pragma unroll
                for (int e = 0; e < 2; e++) {
                    const int n = n0 + warp_n * 64 + nt * 8 + qc * 2 + e;
                    if (n < N) {
                        float v = c[mt][nt][half * 2 + e];
                        if (BIAS)  v += bias[n];
                        if (RES)   v += resid[(size_t)m * N + n];
                        if (GELU_) v = 0.5f * v * (1.0f + erff(v * 0.70710678118654752f));
                        if (POUT) {
                            bf16 hh2, ll2; split2(v, hh2, ll2);
                            Ch[(size_t)m * N + n] = hh2;
                            Cl[(size_t)m * N + n] = ll2;
                        } else {
                            Cf[(size_t)m * N + n] = v;
                        }
                    }
                }
            }
        }
    }
}

// ---------------- weight conversion kernels ----------------------------------
__global__ void convert_plane(const float* __restrict__ src,
                              bf16* __restrict__ dh, bf16* __restrict__ dl,
                              size_t n) {
    size_t i = (size_t)blockIdx.x * 256 + threadIdx.x;
    if (i < n) { bf16 h, l; split2(src[i], h, l); dh[i] = h; dl[i] = l; }
}
// Wq/Wk/Wv -> interleaved [L][3][C][C] layout
__global__ void convert_qkv(const float* __restrict__ src,
                            bf16* __restrict__ dh, bf16* __restrict__ dl,
                            int which) {
    size_t i = (size_t)blockIdx.x * 256 + threadIdx.x;
    if (i < (size_t)LL * CC * CC) {
        size_t layer = i / ((size_t)CC * CC), rest = i % ((size_t)CC * CC);
        size_t o = layer * 3 * CC * CC + (size_t)which * CC * CC + rest;
        bf16 h, l; split2(src[i], h, l); dh[o] = h; dl[o] = l;
    }
}
__global__ void concat_bias(const float* __restrict__ bq, const float* __restrict__ bk,
                            const float* __restrict__ bv, float* __restrict__ dst) {
    int i = blockIdx.x * 256 + threadIdx.x;
    if (i < LL * 3 * CC) {
        int l = i / (3 * CC), r = i % (3 * CC);
        float v = (r < CC) ? bq[l * CC + r]
                : (r < 2 * CC) ? bk[l * CC + r - CC]
                : bv[l * CC + r - 2 * CC];
        dst[i] = v;
    }
}

// ---------------- embedding --------------------------------------------------
__global__ void embed_kernel(const int* __restrict__ idx,
                             const float* __restrict__ tok,
                             const float* __restrict__ pos,
                             float* __restrict__ x) {
    int i = blockIdx.x * blockDim.x + threadIdx.x;
    if (i < BB * TT * CC) {
        int c = i % CC, bt = i / CC, t = bt % TT;
        x[i] = tok[(size_t)idx[bt] * CC + c] + pos[(size_t)t * CC + c];
    }
}

// ---------------- layernorm -> bf16 planes -----------------------------------
__global__ void ln_kernel(const float* __restrict__ in,
                          bf16* __restrict__ oh, bf16* __restrict__ ol,
                          const float* __restrict__ w, const float* __restrict__ b) {
    const int row = blockIdx.x, tid = threadIdx.x;
    const float4 x4 = *(const float4*)(in + (size_t)row * CC + tid * 4);
    __shared__ float red[256];
    red[tid] = x4.x + x4.y + x4.z + x4.w;
    __syncthreads();
    for (int o = 128; o > 0; o >>= 1) { if (tid < o) red[tid] += red[tid + o]; __syncthreads(); }
    const float mu = red[0] * (1.0f / CC);
    __syncthreads();
    const float d0 = x4.x - mu, d1 = x4.y - mu, d2 = x4.z - mu, d3 = x4.w - mu;
    red[tid] = d0 * d0 + d1 * d1 + d2 * d2 + d3 * d3;
    __syncthreads();
    for (int o = 128; o > 0; o >>= 1) { if (tid < o) red[tid] += red[tid + o]; __syncthreads(); }
    const float rstd = rsqrtf(red[0] * (1.0f / CC) + 1e-5f);
    const float4 w4 = *(const float4*)(w + tid * 4);
    const float4 b4 = *(const float4*)(b + tid * 4);
    const size_t o = (size_t)row * CC + tid * 4;
    float v;
    bf16 h, l;
    v = d0 * rstd * w4.x + b4.x; split2(v, h, l); oh[o + 0] = h; ol[o + 0] = l;
    v = d1 * rstd * w4.y + b4.y; split2(v, h, l); oh[o + 1] = h; ol[o + 1] = l;
    v = d2 * rstd * w4.z + b4.z; split2(v, h, l); oh[o + 2] = h; ol[o + 2] = l;
    v = d3 * rstd * w4.w + b4.w; split2(v, h, l); oh[o + 3] = h; ol[o + 3] = l;
}

// ---------------- attention: 8 q-rows per block, chunked K/V -----------------
#define QT 8
#define JCH 128
#define KVROW 68
// smem floats: qs QT*68=544 | kv 128*68=8704 | sc QT*1024=8192 | part 4*8*64=2048 | invs 8
#define ATTN_SMEM ((QT*KVROW + JCH*KVROW + QT*TT + 4*QT*DD + 8) * 4)

__global__ void __launch_bounds__(256)
attn_kernel(const float* __restrict__ qkv, bf16* __restrict__ yh, bf16* __restrict__ yl) {
    extern __shared__ float sf[];
    float* qs   = sf;
    float* kv   = sf + QT * KVROW;
    float* sc   = kv + JCH * KVROW;
    float* part = sc + QT * TT;
    float* invs = part + 4 * QT * DD;

    const int tid = threadIdx.x, lane = tid & 31, wid = tid >> 5;
    const int qb = blockIdx.x * QT;
    const int bh = blockIdx.y, b = bh / HH, h = bh % HH;
    const int RS = 3 * CC;
    const float* qp = qkv + (size_t)(b * TT) * RS + h * DD;
    const float* kp = qp + CC;
    const float* vp = qp + 2 * CC;
    const int lenmax = qb + QT;

    // load q rows (512 floats = 128 float4)
    for (int i = tid; i < QT * 16; i += 256) {
        int r = i >> 4, d4 = i & 15;
        *(float4*)(qs + r * KVROW + 4 * d4) =
            *(const float4*)(qp + (size_t)(qb + r) * RS + 4 * d4);
    }

    // ---- scores ----
    for (int jt = 0; jt < lenmax; jt += JCH) {
        const int nr = min(JCH, lenmax - jt);
        __syncthreads();
        for (int i = tid; i < nr * 16; i += 256) {
            int r = i >> 4, d4 = i & 15;
            *(float4*)(kv + r * KVROW + 4 * d4) =
                *(const float4*)(kp + (size_t)(jt + r) * RS + 4 * d4);
        }
        __syncthreads();
        #pragma unroll
        for (int it = 0; it < 4; it++) {
            const int jj = (tid >> 3) + 32 * it;
            if (jj < nr) {
                const int r = tid & 7;
                const float* kr = kv + jj * KVROW;
                const float* qr = qs + r * KVROW;
                float dot = 0.f;
                #pragma unroll
                for (int d = 0; d < DD; d += 4) {
                    float4 kk = *(const float4*)(kr + d);
                    float4 qq = *(const float4*)(qr + d);
                    dot += kk.x * qq.x + kk.y * qq.y + kk.z * qq.z + kk.w * qq.w;
                }
                sc[r * TT + jt + jj] = dot * 0.125f;
            }
        }
    }
    __syncthreads();

    // ---- softmax: warp w owns row w ----
    {
        const int r = wid;
        const int len = qb + r + 1;
        float mx = -1e30f;
        for (int j = lane; j < len; j += 32) mx = fmaxf(mx, sc[r * TT + j]);
        #pragma unroll
        for (int o = 16; o; o >>= 1) mx = fmaxf(mx, __shfl_xor_sync(~0u, mx, o));
        float sum = 0.f;
        for (int j = lane; j < len; j += 32) {
            float e = __expf(sc[r * TT + j] - mx);
            sc[r * TT + j] = e;
            sum += e;
        }
        #pragma unroll
        for (int o = 16; o; o >>= 1) sum += __shfl_xor_sync(~0u, sum, o);
        for (int j = len + lane; j < lenmax; j += 32) sc[r * TT + j] = 0.f;
        if (lane == 0) invs[r] = 1.0f / sum;
    }
    __syncthreads();

    // ---- V accumulation ----
    const int g = tid >> 6;      // 0..3
    const int d = tid & 63;
    float acc[QT];
    #pragma unroll
    for (int r = 0; r < QT; r++) acc[r] = 0.f;

    for (int jt = 0; jt < lenmax; jt += JCH) {
        const int nr = min(JCH, lenmax - jt);
        __syncthreads();
        for (int i = tid; i < nr * 16; i += 256) {
            int r = i >> 4, d4 = i & 15;
            *(float4*)(kv + r * KVROW + 4 * d4) =
                *(const float4*)(vp + (size_t)(jt + r) * RS + 4 * d4);
        }
        __syncthreads();
        for (int jj = g; jj < nr; jj += 4) {
            const float vv = kv[jj * KVROW + d];
            const int j = jt + jj;
            #pragma unroll
            for (int r = 0; r < QT; r++)
                acc[r] = fmaf(sc[r * TT + j], vv, acc[r]);
        }
    }
    #pragma unroll
    for (int r = 0; r < QT; r++) part[(g * QT + r) * DD + d] = acc[r];
    __syncthreads();

    for (int i = tid; i < QT * DD; i += 256) {
        const int r = i >> 6, dd = i & 63;
        const float v = (part[(0 * QT + r) * DD + dd] + part[(1 * QT + r) * DD + dd] +
                         part[(2 * QT + r) * DD + dd] + part[(3 * QT + r) * DD + dd]) * invs[r];
        const size_t o = (size_t)(b * TT + qb + r) * CC + h * DD + dd;
        bf16 hh2, ll2; split2(v, hh2, ll2);
        yh[o] = hh2; yl[o] = ll2;
    }
}

// ---------------- host orchestration ---------------------------------------
static inline dim3 tc_grid(int M, int N) {
    return dim3((N + 127) / 128, (M + 127) / 128);
}

extern "C" void kernel_launch(void* const* d_in, const int* in_sizes, int n_in,
                              void* d_out, int out_size) {
    const int*   idx    = (const int*)  d_in[0];
    const float* tok    = (const float*)d_in[1];
    const float* pos    = (const float*)d_in[2];
    const float* ln1w   = (const float*)d_in[3];
    const float* ln1b   = (const float*)d_in[4];
    const float* Wq     = (const float*)d_in[5];
    const float* bq     = (const float*)d_in[6];
    const float* Wk     = (const float*)d_in[7];
    const float* bk     = (const float*)d_in[8];
    const float* Wv     = (const float*)d_in[9];
    const float* bv     = (const float*)d_in[10];
    const float* Wo     = (const float*)d_in[11];
    const float* bo     = (const float*)d_in[12];
    const float* ln2w   = (const float*)d_in[13];
    const float* ln2b   = (const float*)d_in[14];
    const float* W1     = (const float*)d_in[15];
    const float* b1     = (const float*)d_in[16];
    const float* W2     = (const float*)d_in[17];
    const float* b2     = (const float*)d_in[18];
    const float* lnfw   = (const float*)d_in[19];
    const float* lnfb   = (const float*)d_in[20];
    const float* head_w = (const float*)d_in[21];
    float* out = (float*)d_out;

    float *x, *qkv, *bqkv;
    bf16 *hh, *hl, *yh, *yl, *h2h, *h2l;
    bf16 *wqkvh, *wqkvl, *woh, *wol, *w1h, *w1l, *w2h, *w2l, *whh, *whl;
    cudaGetSymbolAddress((void**)&x,     g_x);
    cudaGetSymbolAddress((void**)&qkv,   g_qkv);
    cudaGetSymbolAddress((void**)&bqkv,  g_bqkv);
    cudaGetSymbolAddress((void**)&hh,    g_hh);
    cudaGetSymbolAddress((void**)&hl,    g_hl);
    cudaGetSymbolAddress((void**)&yh,    g_yh);
    cudaGetSymbolAddress((void**)&yl,    g_yl);
    cudaGetSymbolAddress((void**)&h2h,   g_h2h);
    cudaGetSymbolAddress((void**)&h2l,   g_h2l);
    cudaGetSymbolAddress((void**)&wqkvh, g_wqkvh);
    cudaGetSymbolAddress((void**)&wqkvl, g_wqkvl);
    cudaGetSymbolAddress((void**)&woh,   g_woh);
    cudaGetSymbolAddress((void**)&wol,   g_wol);
    cudaGetSymbolAddress((void**)&w1h,   g_w1h);
    cudaGetSymbolAddress((void**)&w1l,   g_w1l);
    cudaGetSymbolAddress((void**)&w2h,   g_w2h);
    cudaGetSymbolAddress((void**)&w2l,   g_w2l);
    cudaGetSymbolAddress((void**)&whh,   g_whh);
    cudaGetSymbolAddress((void**)&whl,   g_whl);

    cudaFuncSetAttribute(gemm_mma<true,  false, false, false>, cudaFuncAttributeMaxDynamicSharedMemorySize, GEMM_SMEM);
    cudaFuncSetAttribute(gemm_mma<true,  true,  false, false>, cudaFuncAttributeMaxDynamicSharedMemorySize, GEMM_SMEM);
    cudaFuncSetAttribute(gemm_mma<true,  false, true,  true >, cudaFuncAttributeMaxDynamicSharedMemorySize, GEMM_SMEM);
    cudaFuncSetAttribute(gemm_mma<false, false, false, false>, cudaFuncAttributeMaxDynamicSharedMemorySize, GEMM_SMEM);
    cudaFuncSetAttribute(attn_kernel, cudaFuncAttributeMaxDynamicSharedMemorySize, ATTN_SMEM);

    const int M = BB * TT;      // 2048

    // weight conversions (bf16 hi/lo planes)
    {
        size_t n3 = (size_t)LL * CC * CC;
        int g3 = (int)((n3 + 255) / 256);
        convert_qkv<<<g3, 256>>>(Wq, wqkvh, wqkvl, 0);
        convert_qkv<<<g3, 256>>>(Wk, wqkvh, wqkvl, 1);
        convert_qkv<<<g3, 256>>>(Wv, wqkvh, wqkvl, 2);
        convert_plane<<<g3, 256>>>(Wo, woh, wol, n3);
        size_t n1 = (size_t)LL * FF * CC;
        convert_plane<<<(int)((n1 + 255) / 256), 256>>>(W1, w1h, w1l, n1);
        convert_plane<<<(int)((n1 + 255) / 256), 256>>>(W2, w2h, w2l, n1);
        size_t nh = (size_t)VV * CC;
        convert_plane<<<(int)((nh + 255) / 256), 256>>>(head_w, whh, whl, nh);
        concat_bias<<<(LL * 3 * CC + 255) / 256, 256>>>(bq, bk, bv, bqkv);
    }

    embed_kernel<<<(BB * TT * CC + 255) / 256, 256>>>(idx, tok, pos, x);

    for (int l = 0; l < LL; l++) {
        const size_t o3 = (size_t)l * 3 * CC * CC;
        const size_t o1 = (size_t)l * CC * CC;
        const size_t of = (size_t)l * FF * CC;

        ln_kernel<<<M, 256>>>(x, hh, hl, ln1w + (size_t)l * CC, ln1b + (size_t)l * CC);
        gemm_mma<true, false, false, false><<<tc_grid(M, 3 * CC), 256, GEMM_SMEM>>>(
            hh, hl, wqkvh + o3, wqkvl + o3, bqkv + (size_t)l * 3 * CC, nullptr,
            qkv, nullptr, nullptr, M, 3 * CC, CC);
        attn_kernel<<<dim3(TT / QT, BB * HH), 256, ATTN_SMEM>>>(qkv, yh, yl);
        gemm_mma<true, true, false, false><<<tc_grid(M, CC), 256, GEMM_SMEM>>>(
            yh, yl, woh + o1, wol + o1, bo + (size_t)l * CC, x,
            x, nullptr, nullptr, M, CC, CC);
        ln_kernel<<<M, 256>>>(x, hh, hl, ln2w + (size_t)l * CC, ln2b + (size_t)l * CC);
        gemm_mma<true, false, true, true><<<tc_grid(M, FF), 256, GEMM_SMEM>>>(
            hh, hl, w1h + of, w1l + of, b1 + (size_t)l * FF, nullptr,
            nullptr, h2h, h2l, M, FF, CC);
        gemm_mma<true, true, false, false><<<tc_grid(M, CC), 256, GEMM_SMEM>>>(
            h2h, h2l, w2h + of, w2l + of, b2 + (size_t)l * CC, x,
            x, nullptr, nullptr, M, CC, FF);
    }

    ln_kernel<<<M, 256>>>(x, hh, hl, lnfw, lnfb);
    gemm_mma<false, false, false, false><<<tc_grid(M, VV), 256, GEMM_SMEM>>>(
        hh, hl, whh, whl, nullptr, nullptr,
        out, nullptr, nullptr, M, VV, CC);
}